// round 7
// baseline (speedup 1.0000x reference)
#include <cuda_runtime.h>
#include <cstdint>

// depthconv1d: B=8, L=16384, C=512, K=31, SAME padding, fp32 NWC.
// out[b,w,c] = sum_k x[b, w+k-15, c] * ker[k*C + c] + bias[c]
//
// R6 = R5 with the pipeline-tail fix: commit a (possibly empty) cp.async
// group EVERY iteration so that at iteration i exactly i+2 groups are
// committed and wait_group 1 guarantees group i (the buffer being computed)
// has landed. R5 let the final tile compute against an in-flight load.

#define B_ 8
#define L_ 16384
#define C_ 512
#define K_ 31
#define HALF_ 15
#define T_ 16                   // outputs per thread
#define CB_ 128                 // channels per block
#define WB_ 64                  // output rows per tile (4 grps x T)
#define NITER_ 4                // tiles per CTA
#define NR_ (WB_ + K_ - 1)      // 94 staged rows per buffer
#define ROWB_ (CB_ * 4)         // 512 bytes per staged row
#define BUFB_ (NR_ * ROWB_)     // 48128 B per buffer
#define WSB_ (K_ * ROWB_)       // 15872 B weights
#define SMEM_TOTAL_ (2 * BUFB_ + WSB_)   // 112128 B
#define XW_ 18                  // register x-ring slots
#define NP_ (T_ + K_ - 1)       // 46 rows read per thread per tile

using u64 = unsigned long long;

__device__ __forceinline__ u64 fma2(u64 a, u64 b, u64 c) {
    u64 d;
    asm("fma.rn.f32x2 %0, %1, %2, %3;" : "=l"(d) : "l"(a), "l"(b), "l"(c));
    return d;
}
__device__ __forceinline__ u64 add2(u64 a, u64 b) {
    u64 d;
    asm("add.rn.f32x2 %0, %1, %2;" : "=l"(d) : "l"(a), "l"(b));
    return d;
}
__device__ __forceinline__ void cp_async16(uint32_t sa, const void* g) {
    asm volatile("cp.async.cg.shared.global [%0], [%1], 16;"
                 :: "r"(sa), "l"(g) : "memory");
}
#define CP_COMMIT() asm volatile("cp.async.commit_group;" ::: "memory")
#define CP_WAIT1()  asm volatile("cp.async.wait_group 1;"  ::: "memory")

// Stage NR_=94 rows x 512B into one buffer. 3008 16B chunks over 256 threads.
template <bool EDGE>
__device__ __forceinline__ void load_buf(char* dst, uint32_t dsta,
                                         const char* gx, int row0, int tid)
{
#pragma unroll
    for (int j = 0; j < 12; j++) {
        int chunk = j * 256 + tid;
        if (chunk < NR_ * 32) {
            int r = chunk >> 5, lane = chunk & 31;
            int wg = row0 + r;
            if (!EDGE || ((unsigned)wg < (unsigned)L_)) {
                cp_async16(dsta + r * ROWB_ + lane * 16,
                           gx + (long long)wg * (C_ * 4) + lane * 16);
            } else {
                *reinterpret_cast<uint4*>(dst + r * ROWB_ + lane * 16)
                    = make_uint4(0u, 0u, 0u, 0u);
            }
        }
    }
}

template <bool EDGE>
__device__ __forceinline__ void run_body(
    const float* __restrict__ x, const float* __restrict__ w,
    const float* __restrict__ bias, float* __restrict__ out, char* smem)
{
    char* ws = smem + 2 * BUFB_;
    const int tid = threadIdx.x;
    const int cb0 = blockIdx.y * CB_;
    const int b   = blockIdx.z;
    const int W0  = blockIdx.x * (WB_ * NITER_);

    const char* gx = reinterpret_cast<const char*>(x)
                   + ((long long)b * L_ * C_ + cb0) * 4ll;
    uint32_t sa0 = (uint32_t)__cvta_generic_to_shared(smem);
    uint32_t wsa = sa0 + 2 * BUFB_;

    // ---- Prologue: weights + buf0 (group 0), buf1 (group 1) ----
#pragma unroll
    for (int j = 0; j < 4; j++) {
        int chunk = j * 256 + tid;
        if (chunk < K_ * 32) {
            int k = chunk >> 5, lane = chunk & 31;
            cp_async16(wsa + k * ROWB_ + lane * 16,
                       reinterpret_cast<const char*>(w)
                       + ((long long)k * C_ + cb0) * 4ll + lane * 16);
        }
    }
    load_buf<EDGE>(smem, sa0, gx, W0 - HALF_, tid);
    CP_COMMIT();                                   // G0 = weights + buf0
    load_buf<EDGE>(smem + BUFB_, sa0 + BUFB_, gx, W0 - HALF_ + WB_, tid);
    CP_COMMIT();                                   // G1 = buf1

    const int pair = tid & 63;                     // channel pair 0..63
    const int grp  = tid >> 6;                     // w-subgroup 0..3
    const u64 bv = *reinterpret_cast<const u64*>(bias + cb0 + pair * 2);
    const char* wsp = ws + pair * 8;
    char* ob0 = reinterpret_cast<char*>(out)
              + ((long long)((long long)b * L_ + W0 + grp * T_) * C_
                 + cb0 + pair * 2) * 4ll;

#pragma unroll 1
    for (int i = 0; i < NITER_; i++) {
        // Committed groups so far: i + 2. wait_group 1 -> groups 0..i done,
        // so buffer (i&1) holding tile i is guaranteed landed.
        CP_WAIT1();
        __syncthreads();

        const char* xsp = smem + (i & 1) * BUFB_
                        + (grp * T_) * ROWB_ + pair * 8;

        // k-outer compute with register x-ring sourced from SMEM.
        u64 xv[XW_];
#pragma unroll
        for (int p = 0; p < XW_; p++)
            xv[p] = *reinterpret_cast<const u64*>(xsp + p * ROWB_);

        u64 acc[T_];
#pragma unroll
        for (int t = 0; t < T_; t++) acc[t] = 0ull;

        u64 wcur = *reinterpret_cast<const u64*>(wsp);
#pragma unroll
        for (int k = 0; k < K_; k++) {
            u64 wnext = 0ull;
            if (k + 1 < K_)
                wnext = *reinterpret_cast<const u64*>(wsp + (k + 1) * ROWB_);
#pragma unroll
            for (int t = 0; t < T_; t++)
                acc[t] = fma2(xv[(k + t) % XW_], wcur, acc[t]);
            if (k + XW_ < NP_)
                xv[(k + XW_) % XW_] =
                    *reinterpret_cast<const u64*>(xsp + (k + XW_) * ROWB_);
            wcur = wnext;
        }

        char* ob = ob0 + (long long)i * WB_ * (C_ * 4);
#pragma unroll
        for (int t = 0; t < T_; t++)
            *reinterpret_cast<u64*>(ob + (long long)t * (C_ * 4))
                = add2(acc[t], bv);

        __syncthreads();   // everyone done reading buf(i&1) before refill
        if (i + 2 < NITER_)
            load_buf<EDGE>(smem + (i & 1) * BUFB_, sa0 + (i & 1) * BUFB_,
                           gx, W0 - HALF_ + (i + 2) * WB_, tid);
        CP_COMMIT();       // unconditional: keeps the group ledger in step
    }
}

__global__ __launch_bounds__(256, 2)
void depthconv1d_kernel(const float* __restrict__ x,
                        const float* __restrict__ w,
                        const float* __restrict__ bias,
                        float* __restrict__ out)
{
    extern __shared__ char smem[];
    if (blockIdx.x == 0 || blockIdx.x == gridDim.x - 1)
        run_body<true>(x, w, bias, out, smem);
    else
        run_body<false>(x, w, bias, out, smem);
}

extern "C" void kernel_launch(void* const* d_in, const int* in_sizes, int n_in,
                              void* d_out, int out_size)
{
    const float* x    = (const float*)d_in[0];  // [8, 16384, 512]
    const float* ker  = (const float*)d_in[1];  // [31, 512, 1]
    const float* bias = (const float*)d_in[2];  // [512]
    float* out = (float*)d_out;                 // [8, 16384, 512]

    cudaFuncSetAttribute(depthconv1d_kernel,
                         cudaFuncAttributeMaxDynamicSharedMemorySize,
                         SMEM_TOTAL_);

    dim3 grid(L_ / (WB_ * NITER_), C_ / CB_, B_);   // (64, 4, 8) = 2048
    dim3 block(256);
    depthconv1d_kernel<<<grid, block, SMEM_TOTAL_>>>(x, ker, bias, out);
}